// round 1
// baseline (speedup 1.0000x reference)
#include <cuda_runtime.h>
#include <cstdint>

#define D 128
#define MAXN 100000
#define MAXE 1600000
#define MAXNO 640
#define EPSV 1e-5f
#define LDT 132
#define GEMM_SMEM ((128*LDT + 64*LDT + 256) * 4)

// ---------------- device scratch (static, no runtime alloc) ----------------
__device__ float g_H[(size_t)MAXN * MAXNO];   // [N, T*D] hidden
__device__ float g_tmp[(size_t)MAXN * D];     // round-1 output
__device__ int   g_rowptr[MAXN + 1];
__device__ int   g_cursor[MAXN];              // also used as degree histogram
__device__ int   g_csroff[MAXE];              // per-edge src*NO + etype*D, CSR-ordered by dst
__device__ float g_stats[2 * D];              // sum, sumsq
__device__ float g_ab[2 * D];                 // alpha, beta'

// ---------------- small utility kernels ----------------
__global__ void zero_ints(int* p, int n) {
    int i = blockIdx.x * blockDim.x + threadIdx.x;
    if (i < n) p[i] = 0;
}
__global__ void zero_floats(float* p, int n) {
    int i = blockIdx.x * blockDim.x + threadIdx.x;
    if (i < n) p[i] = 0.f;
}
__global__ void copy_ints(const int* __restrict__ a, int* __restrict__ b, int n) {
    int i = blockIdx.x * blockDim.x + threadIdx.x;
    if (i < n) b[i] = a[i];
}
__global__ void hist_kernel(const int* __restrict__ dst, int* __restrict__ deg, int E) {
    int e = blockIdx.x * blockDim.x + threadIdx.x;
    if (e < E) atomicAdd(&deg[dst[e]], 1);
}

// single-block exclusive scan, 1024 threads, warp-shuffle based
__global__ void scan_kernel(const int* __restrict__ deg, int* __restrict__ rp, int n) {
    __shared__ int warp_sums[32];
    __shared__ int s_carry;
    int tid = threadIdx.x, lane = tid & 31, wid = tid >> 5;
    if (tid == 0) s_carry = 0;
    __syncthreads();
    for (int base = 0; base < n; base += 1024) {
        int i = base + tid;
        int v = (i < n) ? deg[i] : 0;
        int x = v;
        #pragma unroll
        for (int o = 1; o < 32; o <<= 1) {
            int y = __shfl_up_sync(0xFFFFFFFFu, x, o);
            if (lane >= o) x += y;
        }
        if (lane == 31) warp_sums[wid] = x;
        __syncthreads();
        if (wid == 0) {
            int w = warp_sums[lane];
            #pragma unroll
            for (int o = 1; o < 32; o <<= 1) {
                int y = __shfl_up_sync(0xFFFFFFFFu, w, o);
                if (lane >= o) w += y;
            }
            warp_sums[lane] = w;
        }
        __syncthreads();
        int warp_off = (wid > 0) ? warp_sums[wid - 1] : 0;
        int excl = s_carry + warp_off + x - v;
        if (i < n) rp[i] = excl;
        __syncthreads();
        if (tid == 1023) s_carry += warp_off + x;
        __syncthreads();
    }
    if (threadIdx.x == 0) rp[n] = s_carry;
}

__global__ void fill_csr(const int* __restrict__ dst, const int* __restrict__ src,
                         const int* __restrict__ et, int* __restrict__ cursor,
                         int* __restrict__ csroff, int E, int NO) {
    int e = blockIdx.x * blockDim.x + threadIdx.x;
    if (e < E) {
        int pos = atomicAdd(&cursor[dst[e]], 1);
        csroff[pos] = src[e] * NO + et[e] * D;
    }
}

// ---------------- BN stats ----------------
__global__ void colstats(const float* __restrict__ X, float* __restrict__ stats, int N) {
    int d = threadIdx.x;  // 128 threads
    float s = 0.f, s2 = 0.f;
    for (int r = blockIdx.x; r < N; r += gridDim.x) {
        float v = X[(size_t)r * D + d];
        s += v;
        s2 += v * v;
    }
    atomicAdd(&stats[d], s);
    atomicAdd(&stats[D + d], s2);
}

__global__ void finalize_stats(const float* __restrict__ stats, const float* __restrict__ g,
                               const float* __restrict__ be, float* __restrict__ ab, float invN) {
    int d = threadIdx.x;  // 128
    float mu  = stats[d] * invN;
    float var = stats[D + d] * invN - mu * mu;
    float a = g[d] * rsqrtf(var + EPSV);
    ab[d]     = a;
    ab[D + d] = be[d] - a * mu;
}

// ---------------- tf32 GEMM with fused BN+ReLU ----------------
__device__ __forceinline__ float to_tf32(float x) {
    uint32_t u;
    asm("cvt.rna.tf32.f32 %0, %1;" : "=r"(u) : "f"(x));
    return __uint_as_float(u);
}

__device__ __forceinline__ void mma_tf32(float c[4], const uint32_t a[4], const uint32_t b[2]) {
    asm volatile(
        "mma.sync.aligned.m16n8k8.row.col.f32.tf32.tf32.f32 "
        "{%0,%1,%2,%3}, {%4,%5,%6,%7}, {%8,%9}, {%0,%1,%2,%3};\n"
        : "+f"(c[0]), "+f"(c[1]), "+f"(c[2]), "+f"(c[3])
        : "r"(a[0]), "r"(a[1]), "r"(a[2]), "r"(a[3]), "r"(b[0]), "r"(b[1]));
}

// block: 128(M) x 64(N), 256 threads, warps 4x2, warp tile 32x32 (2 mtiles x 4 ntiles)
__global__ void gemm_bn_relu(const float* __restrict__ X, const float* __restrict__ W,
                             const float* __restrict__ bias, const float* __restrict__ ab,
                             float* __restrict__ H, int Nrows, int NO) {
    extern __shared__ float sm[];
    float* As  = sm;                       // [128][LDT]
    float* Bs  = sm + 128 * LDT;           // [64][LDT]
    float* sab = sm + 128 * LDT + 64 * LDT;  // [256]

    int tid = threadIdx.x;
    sab[tid] = ab[tid];
    __syncthreads();

    int row0 = blockIdx.x * 128;
    int col0 = blockIdx.y * 64;

    // load A (x rows) with fused BN+ReLU+tf32
    #pragma unroll
    for (int i = 0; i < 16; i++) {
        int idx = tid + i * 256;
        int r = idx >> 5, kc = idx & 31;
        int gr = row0 + r;
        float4 v = make_float4(0.f, 0.f, 0.f, 0.f);
        if (gr < Nrows) v = __ldg((const float4*)(X + (size_t)gr * D) + kc);
        int k = kc * 4;
        float a0 = sab[k], a1 = sab[k + 1], a2 = sab[k + 2], a3 = sab[k + 3];
        float p0 = sab[D + k], p1 = sab[D + k + 1], p2 = sab[D + k + 2], p3 = sab[D + k + 3];
        v.x = to_tf32(fmaxf(fmaf(a0, v.x, p0), 0.f));
        v.y = to_tf32(fmaxf(fmaf(a1, v.y, p1), 0.f));
        v.z = to_tf32(fmaxf(fmaf(a2, v.z, p2), 0.f));
        v.w = to_tf32(fmaxf(fmaf(a3, v.w, p3), 0.f));
        *(float4*)(As + r * LDT + k) = v;
    }
    // load B (w rows = output neurons), tf32
    #pragma unroll
    for (int i = 0; i < 8; i++) {
        int idx = tid + i * 256;
        int r = idx >> 5, kc = idx & 31;
        float4 v = __ldg((const float4*)(W + (size_t)(col0 + r) * D) + kc);
        v.x = to_tf32(v.x); v.y = to_tf32(v.y); v.z = to_tf32(v.z); v.w = to_tf32(v.w);
        *(float4*)(Bs + r * LDT + kc * 4) = v;
    }
    __syncthreads();

    int warp = tid >> 5, lane = tid & 31;
    int wm = warp >> 1, wn = warp & 1;
    int wrow = wm * 32, wcol = wn * 32;
    int gid = lane >> 2, tig = lane & 3;

    float c[2][4][4];
    #pragma unroll
    for (int mt = 0; mt < 2; mt++)
        #pragma unroll
        for (int nt = 0; nt < 4; nt++)
            #pragma unroll
            for (int q = 0; q < 4; q++) c[mt][nt][q] = 0.f;

    #pragma unroll
    for (int k0 = 0; k0 < 128; k0 += 8) {
        uint32_t a[2][4], b[4][2];
        #pragma unroll
        for (int mt = 0; mt < 2; mt++) {
            int r = wrow + mt * 16 + gid;
            a[mt][0] = __float_as_uint(As[r * LDT + k0 + tig]);
            a[mt][1] = __float_as_uint(As[(r + 8) * LDT + k0 + tig]);
            a[mt][2] = __float_as_uint(As[r * LDT + k0 + tig + 4]);
            a[mt][3] = __float_as_uint(As[(r + 8) * LDT + k0 + tig + 4]);
        }
        #pragma unroll
        for (int nt = 0; nt < 4; nt++) {
            int n = wcol + nt * 8 + gid;
            b[nt][0] = __float_as_uint(Bs[n * LDT + k0 + tig]);
            b[nt][1] = __float_as_uint(Bs[n * LDT + k0 + tig + 4]);
        }
        #pragma unroll
        for (int mt = 0; mt < 2; mt++)
            #pragma unroll
            for (int nt = 0; nt < 4; nt++)
                mma_tf32(c[mt][nt], a[mt], b[nt]);
    }

    // epilogue: bias add + store
    #pragma unroll
    for (int mt = 0; mt < 2; mt++) {
        int r = row0 + wrow + mt * 16 + gid;
        #pragma unroll
        for (int nt = 0; nt < 4; nt++) {
            int col = col0 + wcol + nt * 8 + 2 * tig;
            float b0 = __ldg(&bias[col]), b1 = __ldg(&bias[col + 1]);
            if (r < Nrows) {
                float2 v = make_float2(c[mt][nt][0] + b0, c[mt][nt][1] + b1);
                *(float2*)(H + (size_t)r * NO + col) = v;
            }
            if (r + 8 < Nrows) {
                float2 v = make_float2(c[mt][nt][2] + b0, c[mt][nt][3] + b1);
                *(float2*)(H + (size_t)(r + 8) * NO + col) = v;
            }
        }
    }
}

// ---------------- CSR gather-aggregate: 1 warp per dst node ----------------
__global__ void aggregate(const float* __restrict__ H, const int* __restrict__ rp,
                          const int* __restrict__ csroff, const float* __restrict__ addend,
                          float* __restrict__ out, int N) {
    int w = (blockIdx.x * blockDim.x + threadIdx.x) >> 5;
    int lane = threadIdx.x & 31;
    if (w >= N) return;
    int beg = rp[w], end = rp[w + 1];
    float4 acc = make_float4(0.f, 0.f, 0.f, 0.f);
    int off = (beg < end) ? __ldg(&csroff[beg]) : 0;
    for (int i = beg; i < end; i++) {
        int off_next = (i + 1 < end) ? __ldg(&csroff[i + 1]) : 0;
        float4 v = __ldg((const float4*)(H + off) + lane);
        acc.x += v.x; acc.y += v.y; acc.z += v.z; acc.w += v.w;
        off = off_next;
    }
    if (addend) {
        float4 a = __ldg((const float4*)(addend + (size_t)w * D) + lane);
        acc.x += a.x; acc.y += a.y; acc.z += a.z; acc.w += a.w;
    }
    ((float4*)(out + (size_t)w * D))[lane] = acc;
}

// ---------------- launch ----------------
extern "C" void kernel_launch(void* const* d_in, const int* in_sizes, int n_in,
                              void* d_out, int out_size) {
    const float* features = (const float*)d_in[0];
    const int*   src      = (const int*)d_in[1];
    const int*   dst      = (const int*)d_in[2];
    const int*   etype    = (const int*)d_in[3];
    const float* w1       = (const float*)d_in[4];
    const float* b1       = (const float*)d_in[5];
    const float* g1       = (const float*)d_in[6];
    const float* be1      = (const float*)d_in[7];
    const float* w2       = (const float*)d_in[8];
    const float* b2       = (const float*)d_in[9];
    const float* g2       = (const float*)d_in[10];
    const float* be2      = (const float*)d_in[11];

    int N  = in_sizes[0] / D;
    int E  = in_sizes[1];
    int NO = in_sizes[5];  // T*D

    float *H, *tmp, *stats, *ab;
    int *rp, *cur, *coff;
    cudaGetSymbolAddress((void**)&H, g_H);
    cudaGetSymbolAddress((void**)&tmp, g_tmp);
    cudaGetSymbolAddress((void**)&stats, g_stats);
    cudaGetSymbolAddress((void**)&ab, g_ab);
    cudaGetSymbolAddress((void**)&rp, g_rowptr);
    cudaGetSymbolAddress((void**)&cur, g_cursor);
    cudaGetSymbolAddress((void**)&coff, g_csroff);

    cudaFuncSetAttribute(gemm_bn_relu, cudaFuncAttributeMaxDynamicSharedMemorySize, GEMM_SMEM);

    // CSR build (shared by both rounds)
    zero_ints<<<(N + 511) / 512, 512>>>(cur, N);
    hist_kernel<<<(E + 255) / 256, 256>>>(dst, cur, E);
    scan_kernel<<<1, 1024>>>(cur, rp, N);
    copy_ints<<<(N + 511) / 512, 512>>>(rp, cur, N);
    fill_csr<<<(E + 255) / 256, 256>>>(dst, src, etype, cur, coff, E, NO);

    dim3 gg((N + 127) / 128, NO / 64);
    int agg_blocks = (N * 32 + 255) / 256;

    // round 1
    zero_floats<<<1, 256>>>(stats, 2 * D);
    colstats<<<1184, 128>>>(features, stats, N);
    finalize_stats<<<1, 128>>>(stats, g1, be1, ab, 1.0f / (float)N);
    gemm_bn_relu<<<gg, 256, GEMM_SMEM>>>(features, w1, b1, ab, H, N, NO);
    aggregate<<<agg_blocks, 256>>>(H, rp, coff, nullptr, tmp, N);

    // round 2
    zero_floats<<<1, 256>>>(stats, 2 * D);
    colstats<<<1184, 128>>>(tmp, stats, N);
    finalize_stats<<<1, 128>>>(stats, g2, be2, ab, 1.0f / (float)N);
    gemm_bn_relu<<<gg, 256, GEMM_SMEM>>>(tmp, w2, b2, ab, H, N, NO);
    aggregate<<<agg_blocks, 256>>>(H, rp, coff, features, (float*)d_out, N);
}

// round 3
// speedup vs baseline: 1.2395x; 1.2395x over previous
#include <cuda_runtime.h>
#include <cstdint>

#define D 128
#define T5 5
#define MAXN 100000
#define MAXNP 100096            // padded to 782*128 for GEMM tiles
#define MAXE 1600000
#define NOUT 640                // T*D
#define NBPAD (124 * 4096)      // 507904 (scan coverage, >= 500000 bins)
#define WSZ (NOUT * D)          // 81920 weights per layer
#define EPSV 1e-5f
#define LDA 36
#define GEMM_SMEM (2 * 2 * 128 * LDA * 4)   // 73728 bytes

// ---------------- device scratch (static; no runtime alloc) ----------------
__device__ float g_A[(size_t)MAXNP * NOUT];   // aggregated pre-GEMM activations (tf32), ~256 MB
__device__ float g_tmp[(size_t)MAXN * D];     // round-1 output
__device__ float g_Wc[2 * WSZ];               // tf32-converted weights
__device__ int   g_deg[NBPAD];                // zero-init; hist adds, fill subtracts back to 0
__device__ int   g_local[NBPAD];              // per-4096-block exclusive scan
__device__ int   g_bsum[128];                 // block sums
__device__ int   g_coarse[130];               // coarse exclusive scan
__device__ int   g_srcl[MAXE];                // src node id per edge, sorted by (dst,etype)
__device__ float g_cntf[MAXN * T5];           // edge count per (node,type) as float
__device__ float g_stats[2 * D];              // sum, sumsq (self-resetting)
__device__ float g_ab[2 * D];                 // alpha, beta'
__device__ unsigned int g_ticket;             // self-resetting block counter

// ---------------- helpers ----------------
__device__ __forceinline__ float to_tf32(float x) {
    uint32_t u;
    asm("cvt.rna.tf32.f32 %0, %1;" : "=r"(u) : "f"(x));
    return __uint_as_float(u);
}
__device__ __forceinline__ void cp_async16(void* smem_dst, const void* gmem_src) {
    uint32_t s = (uint32_t)__cvta_generic_to_shared(smem_dst);
    asm volatile("cp.async.cg.shared.global [%0], [%1], 16;\n" :: "r"(s), "l"(gmem_src));
}
#define CP_COMMIT() asm volatile("cp.async.commit_group;\n" ::: "memory")
#define CP_WAIT0()  asm volatile("cp.async.wait_group 0;\n" ::: "memory")

__device__ __forceinline__ void mma_tf32(float c[4], const uint32_t a[4], const uint32_t b[2]) {
    asm volatile(
        "mma.sync.aligned.m16n8k8.row.col.f32.tf32.tf32.f32 "
        "{%0,%1,%2,%3}, {%4,%5,%6,%7}, {%8,%9}, {%0,%1,%2,%3};\n"
        : "+f"(c[0]), "+f"(c[1]), "+f"(c[2]), "+f"(c[3])
        : "r"(a[0]), "r"(a[1]), "r"(a[2]), "r"(a[3]), "r"(b[0]), "r"(b[1]));
}

// ---------------- CSR build over (dst,etype) bins ----------------
__global__ void hist_kernel(const int* __restrict__ dst, const int* __restrict__ et, int E) {
    int e = blockIdx.x * blockDim.x + threadIdx.x;
    if (e < E) atomicAdd(&g_deg[dst[e] * T5 + et[e]], 1);
}

// 124 blocks x 1024 threads x 4 elems: local exclusive scan + block sum
__global__ void scan_local(void) {
    __shared__ int ws[32];
    int b = blockIdx.x, tid = threadIdx.x, lane = tid & 31, wid = tid >> 5;
    int4 v = ((const int4*)g_deg)[b * 1024 + tid];
    int s = v.x + v.y + v.z + v.w;
    int x = s;
    #pragma unroll
    for (int o = 1; o < 32; o <<= 1) {
        int y = __shfl_up_sync(0xFFFFFFFFu, x, o);
        if (lane >= o) x += y;
    }
    if (lane == 31) ws[wid] = x;
    __syncthreads();
    if (wid == 0) {
        int w = ws[lane];
        #pragma unroll
        for (int o = 1; o < 32; o <<= 1) {
            int y = __shfl_up_sync(0xFFFFFFFFu, w, o);
            if (lane >= o) w += y;
        }
        ws[lane] = w;
    }
    __syncthreads();
    int excl = (wid ? ws[wid - 1] : 0) + x - s;
    int4 o;
    o.x = excl; o.y = excl + v.x; o.z = o.y + v.y; o.w = o.z + v.z;
    ((int4*)g_local)[b * 1024 + tid] = o;
    if (tid == 1023) g_bsum[b] = excl + s;
}

__global__ void scan_coarse(void) {
    __shared__ int ws[4];
    int tid = threadIdx.x, lane = tid & 31, wid = tid >> 5;  // 128 threads
    int v = (tid < 124) ? g_bsum[tid] : 0;
    int x = v;
    #pragma unroll
    for (int o = 1; o < 32; o <<= 1) {
        int y = __shfl_up_sync(0xFFFFFFFFu, x, o);
        if (lane >= o) x += y;
    }
    if (lane == 31) ws[wid] = x;
    __syncthreads();
    int woff = 0;
    for (int i = 0; i < wid; i++) woff += ws[i];
    if (tid < 125) g_coarse[tid] = woff + x - v;
}

__device__ __forceinline__ int rp_of(int bin) {
    return g_coarse[bin >> 12] + g_local[bin];
}

__global__ void fill_csr(const int* __restrict__ dst, const int* __restrict__ et,
                         const int* __restrict__ src, int E) {
    int e = blockIdx.x * blockDim.x + threadIdx.x;
    if (e < E) {
        int bin = dst[e] * T5 + et[e];
        int base = rp_of(bin);
        int old = atomicSub(&g_deg[bin], 1);   // deg returns to 0 => self-cleaning
        g_srcl[base + old - 1] = src[e];
    }
}

// ---------------- fused BN column stats (single launch, last-block finalize) ----------------
__global__ void colstats(const float* __restrict__ X, const float* __restrict__ g,
                         const float* __restrict__ be, int N) {
    int d = threadIdx.x;  // 128
    float s = 0.f, s2 = 0.f;
    for (int r = blockIdx.x; r < N; r += gridDim.x) {
        float v = X[(size_t)r * D + d];
        s += v; s2 += v * v;
    }
    atomicAdd(&g_stats[d], s);
    atomicAdd(&g_stats[D + d], s2);
    __threadfence();
    __shared__ unsigned int ticket;
    if (d == 0) ticket = atomicInc(&g_ticket, gridDim.x - 1);  // wraps to 0 on last
    __syncthreads();
    if (ticket == gridDim.x - 1) {
        float invN = 1.0f / (float)N;
        float su  = atomicAdd(&g_stats[d], 0.f);
        float sq  = atomicAdd(&g_stats[D + d], 0.f);
        float mu  = su * invN;
        float var = sq * invN - mu * mu;
        float a = g[d] * rsqrtf(var + EPSV);
        g_ab[d]     = a;
        g_ab[D + d] = be[d] - a * mu;
        g_stats[d] = 0.f; g_stats[D + d] = 0.f;   // ready for next use
    }
}

// ---------------- aggregate: warp per node, BN+ReLU on gather, tf32 output ----------------
// src-index prefetch one edge ahead to overlap index load with row fetch.
__global__ void aggregate(const float* __restrict__ X, int N) {
    int w = (blockIdx.x * blockDim.x + threadIdx.x) >> 5;
    int lane = threadIdx.x & 31;
    if (w >= N) return;
    float4 al = ((const float4*)g_ab)[lane];
    float4 bt = ((const float4*)(g_ab + D))[lane];
    int bin0 = w * T5;
    int rpv[6];
    #pragma unroll
    for (int i = 0; i < 6; i++) rpv[i] = rp_of(bin0 + i);

    float* Arow = g_A + (size_t)w * NOUT;
    #pragma unroll
    for (int t = 0; t < T5; t++) {
        int beg = rpv[t], end = rpv[t + 1];
        float4 acc = make_float4(0.f, 0.f, 0.f, 0.f);
        int s = (beg < end) ? __ldg(&g_srcl[beg]) : 0;
        for (int e = beg; e < end; e++) {
            int s_next = (e + 1 < end) ? __ldg(&g_srcl[e + 1]) : 0;
            float4 v = __ldg((const float4*)(X + (size_t)s * D) + lane);
            acc.x += fmaxf(fmaf(al.x, v.x, bt.x), 0.f);
            acc.y += fmaxf(fmaf(al.y, v.y, bt.y), 0.f);
            acc.z += fmaxf(fmaf(al.z, v.z, bt.z), 0.f);
            acc.w += fmaxf(fmaf(al.w, v.w, bt.w), 0.f);
            s = s_next;
        }
        acc.x = to_tf32(acc.x); acc.y = to_tf32(acc.y);
        acc.z = to_tf32(acc.z); acc.w = to_tf32(acc.w);
        ((float4*)(Arow + t * D))[lane] = acc;
        if (lane == 0) g_cntf[bin0 + t] = (float)(end - beg);
    }
}

// ---------------- weight tf32 pre-conversion (both layers, one launch) ----------------
__global__ void cvtW(const float* __restrict__ w1, const float* __restrict__ w2) {
    int i = blockIdx.x * blockDim.x + threadIdx.x;
    if (i < WSZ) {
        g_Wc[i]       = to_tf32(w1[i]);
        g_Wc[WSZ + i] = to_tf32(w2[i]);
    }
}

// ---------------- tall GEMM: out[128 x 128] tile, K = 640, cp.async double buffer ----------------
__global__ void __launch_bounds__(256, 2) gemm_agg(
    const float* __restrict__ W, const float* __restrict__ bias,
    const float* __restrict__ addend, float* __restrict__ out, int Nrows) {
    extern __shared__ float sm[];
    int tid = threadIdx.x;
    int row0 = blockIdx.x * 128;
    const float* Agl = g_A + (size_t)row0 * NOUT;

    int warp = tid >> 5, lane = tid & 31;
    int wm = warp >> 2, wn = warp & 3;           // 2x4 warps, warp tile 64x32
    int wrow = wm * 64, wcol = wn * 32;
    int gid = lane >> 2, tig = lane & 3;

    float c[4][4][4];
    #pragma unroll
    for (int mt = 0; mt < 4; mt++)
        #pragma unroll
        for (int nt = 0; nt < 4; nt++)
            #pragma unroll
            for (int q = 0; q < 4; q++) c[mt][nt][q] = 0.f;

    const int NC = NOUT / 32;  // 20 chunks

    auto load_chunk = [&](int cidx, int buf) {
        int k0 = cidx * 32;
        int t = k0 >> 7, kd = k0 & 127;
        float* as = sm + buf * (2 * 128 * LDA);
        float* bs = as + 128 * LDA;
        const float* Asrc = Agl + k0;
        const float* Bsrc = W + ((size_t)t * 128) * 128 + kd;
        #pragma unroll
        for (int i = 0; i < 4; i++) {
            int gnum = tid + i * 256;
            int r = gnum >> 3, sg = gnum & 7;
            cp_async16(as + r * LDA + sg * 4, Asrc + (size_t)r * NOUT + sg * 4);
        }
        #pragma unroll
        for (int i = 0; i < 4; i++) {
            int gnum = tid + i * 256;
            int j = gnum >> 3, sg = gnum & 7;
            cp_async16(bs + j * LDA + sg * 4, Bsrc + (size_t)j * 128 + sg * 4);
        }
        CP_COMMIT();
    };

    load_chunk(0, 0);
    for (int cidx = 0; cidx < NC; cidx++) {
        CP_WAIT0();
        __syncthreads();
        if (cidx + 1 < NC) load_chunk(cidx + 1, (cidx + 1) & 1);
        const float* as = sm + (cidx & 1) * (2 * 128 * LDA);
        const float* bs = as + 128 * LDA;
        #pragma unroll
        for (int ks = 0; ks < 4; ks++) {
            int kk = ks * 8;
            uint32_t a[4][4], b[4][2];
            #pragma unroll
            for (int mt = 0; mt < 4; mt++) {
                int r = wrow + mt * 16 + gid;
                a[mt][0] = __float_as_uint(as[r * LDA + kk + tig]);
                a[mt][1] = __float_as_uint(as[(r + 8) * LDA + kk + tig]);
                a[mt][2] = __float_as_uint(as[r * LDA + kk + tig + 4]);
                a[mt][3] = __float_as_uint(as[(r + 8) * LDA + kk + tig + 4]);
            }
            #pragma unroll
            for (int nt = 0; nt < 4; nt++) {
                int j = wcol + nt * 8 + gid;
                b[nt][0] = __float_as_uint(bs[j * LDA + kk + tig]);
                b[nt][1] = __float_as_uint(bs[j * LDA + kk + tig + 4]);
            }
            #pragma unroll
            for (int mt = 0; mt < 4; mt++)
                #pragma unroll
                for (int nt = 0; nt < 4; nt++)
                    mma_tf32(c[mt][nt], a[mt], b[nt]);
        }
        __syncthreads();
    }

    // epilogue: per-(node,type) count x bias + optional residual
    float* cntS = sm;         // [128][5]
    float* bsm  = sm + 640;   // [5][128] (= bias layout t*128+j)
    for (int i = tid; i < 640; i += 256) {
        int r = i / T5, t = i % T5;
        int gr = row0 + r;
        cntS[i] = (gr < Nrows) ? g_cntf[gr * T5 + t] : 0.f;
        bsm[i] = __ldg(&bias[i]);
    }
    __syncthreads();

    #pragma unroll
    for (int mt = 0; mt < 4; mt++) {
        #pragma unroll
        for (int half = 0; half < 2; half++) {
            int r = wrow + mt * 16 + gid + half * 8;   // 0..127
            int grow = row0 + r;
            if (grow >= Nrows) continue;
            #pragma unroll
            for (int nt = 0; nt < 4; nt++) {
                int j = wcol + nt * 8 + 2 * tig;
                float b0 = 0.f, b1 = 0.f;
                #pragma unroll
                for (int t = 0; t < T5; t++) {
                    float cn = cntS[r * T5 + t];
                    b0 = fmaf(cn, bsm[t * 128 + j], b0);
                    b1 = fmaf(cn, bsm[t * 128 + j + 1], b1);
                }
                float v0 = c[mt][nt][half * 2]     + b0;
                float v1 = c[mt][nt][half * 2 + 1] + b1;
                if (addend) {
                    float2 ad = *(const float2*)(addend + (size_t)grow * D + j);
                    v0 += ad.x; v1 += ad.y;
                }
                *(float2*)(out + (size_t)grow * D + j) = make_float2(v0, v1);
            }
        }
    }
}

// ---------------- launch ----------------
extern "C" void kernel_launch(void* const* d_in, const int* in_sizes, int n_in,
                              void* d_out, int out_size) {
    const float* features = (const float*)d_in[0];
    const int*   src      = (const int*)d_in[1];
    const int*   dst      = (const int*)d_in[2];
    const int*   etype    = (const int*)d_in[3];
    const float* w1       = (const float*)d_in[4];
    const float* b1       = (const float*)d_in[5];
    const float* g1       = (const float*)d_in[6];
    const float* be1      = (const float*)d_in[7];
    const float* w2       = (const float*)d_in[8];
    const float* b2       = (const float*)d_in[9];
    const float* g2       = (const float*)d_in[10];
    const float* be2      = (const float*)d_in[11];

    int N = in_sizes[0] / D;
    int E = in_sizes[1];

    float* tmp;
    float* Wc;
    cudaGetSymbolAddress((void**)&tmp, g_tmp);
    cudaGetSymbolAddress((void**)&Wc, g_Wc);

    cudaFuncSetAttribute(gemm_agg, cudaFuncAttributeMaxDynamicSharedMemorySize, GEMM_SMEM);

    int gemm_blocks = (N + 127) / 128;
    int agg_blocks  = (N * 32 + 255) / 256;

    hist_kernel<<<(E + 255) / 256, 256>>>(dst, etype, E);         // 0
    scan_local<<<124, 1024>>>();                                  // 1
    scan_coarse<<<1, 128>>>();                                    // 2
    fill_csr<<<(E + 255) / 256, 256>>>(dst, etype, src, E);       // 3
    colstats<<<1184, 128>>>(features, g1, be1, N);                // 4
    aggregate<<<agg_blocks, 256>>>(features, N);                  // 5  <- ncu -s 5 profiles this
    cvtW<<<(WSZ + 255) / 256, 256>>>(w1, w2);                     // 6
    gemm_agg<<<gemm_blocks, 256, GEMM_SMEM>>>(Wc, b1, nullptr, tmp, N);                   // 7
    colstats<<<1184, 128>>>(tmp, g2, be2, N);                     // 8
    aggregate<<<agg_blocks, 256>>>(tmp, N);                       // 9
    gemm_agg<<<gemm_blocks, 256, GEMM_SMEM>>>(Wc + WSZ, b2, features, (float*)d_out, N);  // 10
}

// round 5
// speedup vs baseline: 1.6256x; 1.3114x over previous
#include <cuda_runtime.h>
#include <cuda_fp16.h>
#include <cstdint>

#define D 128
#define T5 5
#define MAXN 100000
#define MAXNP 100096            // padded to 782*128 for GEMM tiles
#define MAXE 1600000
#define NOUT 640                // T*D
#define NBPAD (124 * 4096)      // 507904 (scan coverage, >= 500000 bins)
#define WSZ (NOUT * D)          // 81920 weights per layer
#define EPSV 1e-5f
#define LDH 72                  // half elements per smem row (64 + 8 pad)
#define GEMM_SMEM (2 * 2 * 128 * LDH * 2)   // 73728 bytes (A+B, double buffered, fp16)

// ---------------- device scratch (static; no runtime alloc) ----------------
__device__ __half g_Ah[(size_t)MAXNP * NOUT]; // aggregated pre-GEMM activations (fp16), ~128 MB
__device__ float g_tmp[(size_t)MAXN * D];     // round-1 output
__device__ __half g_Wh[2 * WSZ];              // fp16 weights (both layers)
__device__ int   g_deg[NBPAD];                // zero-init; hist adds, fill subtracts back to 0
__device__ int   g_local[NBPAD];              // per-4096-block exclusive scan
__device__ int   g_bsum[128];                 // block sums
__device__ int   g_coarse[130];               // coarse exclusive scan
__device__ int   g_srcl[MAXE];                // src node id per edge, sorted by (dst,etype)
__device__ float g_cntf[MAXN * T5];           // edge count per (node,type) as float
__device__ float g_stats[2 * D];              // sum, sumsq (self-resetting)
__device__ float g_ab[2 * D];                 // alpha, beta'
__device__ unsigned int g_ticket;             // self-resetting block counter (colstats)
__device__ unsigned int g_ticket2;            // self-resetting block counter (gemm stats)

// ---------------- helpers ----------------
__device__ __forceinline__ void cp_async16(void* smem_dst, const void* gmem_src) {
    uint32_t s = (uint32_t)__cvta_generic_to_shared(smem_dst);
    asm volatile("cp.async.cg.shared.global [%0], [%1], 16;\n" :: "r"(s), "l"(gmem_src));
}
#define CP_COMMIT() asm volatile("cp.async.commit_group;\n" ::: "memory")
#define CP_WAIT0()  asm volatile("cp.async.wait_group 0;\n" ::: "memory")

__device__ __forceinline__ void mma_f16(float c[4], const uint32_t a[4], const uint32_t b[2]) {
    asm volatile(
        "mma.sync.aligned.m16n8k16.row.col.f32.f16.f16.f32 "
        "{%0,%1,%2,%3}, {%4,%5,%6,%7}, {%8,%9}, {%0,%1,%2,%3};\n"
        : "+f"(c[0]), "+f"(c[1]), "+f"(c[2]), "+f"(c[3])
        : "r"(a[0]), "r"(a[1]), "r"(a[2]), "r"(a[3]), "r"(b[0]), "r"(b[1]));
}

// ---------------- CSR build over (dst,etype) bins ----------------
__global__ void hist_kernel(const int* __restrict__ dst, const int* __restrict__ et, int E) {
    int e = blockIdx.x * blockDim.x + threadIdx.x;
    if (e < E) atomicAdd(&g_deg[dst[e] * T5 + et[e]], 1);
}

__global__ void scan_local(void) {
    __shared__ int ws[32];
    int b = blockIdx.x, tid = threadIdx.x, lane = tid & 31, wid = tid >> 5;
    int4 v = ((const int4*)g_deg)[b * 1024 + tid];
    int s = v.x + v.y + v.z + v.w;
    int x = s;
    #pragma unroll
    for (int o = 1; o < 32; o <<= 1) {
        int y = __shfl_up_sync(0xFFFFFFFFu, x, o);
        if (lane >= o) x += y;
    }
    if (lane == 31) ws[wid] = x;
    __syncthreads();
    if (wid == 0) {
        int w = ws[lane];
        #pragma unroll
        for (int o = 1; o < 32; o <<= 1) {
            int y = __shfl_up_sync(0xFFFFFFFFu, w, o);
            if (lane >= o) w += y;
        }
        ws[lane] = w;
    }
    __syncthreads();
    int excl = (wid ? ws[wid - 1] : 0) + x - s;
    int4 o;
    o.x = excl; o.y = excl + v.x; o.z = o.y + v.y; o.w = o.z + v.z;
    ((int4*)g_local)[b * 1024 + tid] = o;
    if (tid == 1023) g_bsum[b] = excl + s;
}

__global__ void scan_coarse(void) {
    __shared__ int ws[4];
    int tid = threadIdx.x, lane = tid & 31, wid = tid >> 5;  // 128 threads
    int v = (tid < 124) ? g_bsum[tid] : 0;
    int x = v;
    #pragma unroll
    for (int o = 1; o < 32; o <<= 1) {
        int y = __shfl_up_sync(0xFFFFFFFFu, x, o);
        if (lane >= o) x += y;
    }
    if (lane == 31) ws[wid] = x;
    __syncthreads();
    int woff = 0;
    for (int i = 0; i < wid; i++) woff += ws[i];
    if (tid < 125) g_coarse[tid] = woff + x - v;
}

__device__ __forceinline__ int rp_of(int bin) {
    return g_coarse[bin >> 12] + g_local[bin];
}

__global__ void fill_csr(const int* __restrict__ dst, const int* __restrict__ et,
                         const int* __restrict__ src, int E) {
    int e = blockIdx.x * blockDim.x + threadIdx.x;
    if (e < E) {
        int bin = dst[e] * T5 + et[e];
        int base = rp_of(bin);
        int old = atomicSub(&g_deg[bin], 1);   // deg returns to 0 => self-cleaning
        g_srcl[base + old - 1] = src[e];
    }
}

// ---------------- fused BN column stats (single launch, last-block finalize) ----------------
__global__ void colstats(const float* __restrict__ X, const float* __restrict__ g,
                         const float* __restrict__ be, int N) {
    int d = threadIdx.x;  // 128
    float s = 0.f, s2 = 0.f;
    for (int r = blockIdx.x; r < N; r += gridDim.x) {
        float v = X[(size_t)r * D + d];
        s += v; s2 += v * v;
    }
    atomicAdd(&g_stats[d], s);
    atomicAdd(&g_stats[D + d], s2);
    __threadfence();
    __shared__ unsigned int ticket;
    if (d == 0) ticket = atomicInc(&g_ticket, gridDim.x - 1);  // wraps to 0 on last
    __syncthreads();
    if (ticket == gridDim.x - 1) {
        float invN = 1.0f / (float)N;
        float su  = atomicAdd(&g_stats[d], 0.f);
        float sq  = atomicAdd(&g_stats[D + d], 0.f);
        float mu  = su * invN;
        float var = sq * invN - mu * mu;
        float a = g[d] * rsqrtf(var + EPSV);
        g_ab[d]     = a;
        g_ab[D + d] = be[d] - a * mu;
        g_stats[d] = 0.f; g_stats[D + d] = 0.f;
    }
}

// ---------------- aggregate: warp per node, BN+ReLU on gather, fp16 output ----------------
__global__ void aggregate(const float* __restrict__ X, int N) {
    int w = (blockIdx.x * blockDim.x + threadIdx.x) >> 5;
    int lane = threadIdx.x & 31;
    if (w >= N) return;
    float4 al = ((const float4*)g_ab)[lane];
    float4 bt = ((const float4*)(g_ab + D))[lane];
    int bin0 = w * T5;
    int rpv[6];
    #pragma unroll
    for (int i = 0; i < 6; i++) rpv[i] = rp_of(bin0 + i);

    __half* Arow = g_Ah + (size_t)w * NOUT;
    #pragma unroll
    for (int t = 0; t < T5; t++) {
        int beg = rpv[t], end = rpv[t + 1];
        float4 acc = make_float4(0.f, 0.f, 0.f, 0.f);
        int s = (beg < end) ? __ldg(&g_srcl[beg]) : 0;
        for (int e = beg; e < end; e++) {
            int s_next = (e + 1 < end) ? __ldg(&g_srcl[e + 1]) : 0;
            float4 v = __ldg((const float4*)(X + (size_t)s * D) + lane);
            acc.x += fmaxf(fmaf(al.x, v.x, bt.x), 0.f);
            acc.y += fmaxf(fmaf(al.y, v.y, bt.y), 0.f);
            acc.z += fmaxf(fmaf(al.z, v.z, bt.z), 0.f);
            acc.w += fmaxf(fmaf(al.w, v.w, bt.w), 0.f);
            s = s_next;
        }
        __half2 h01 = __floats2half2_rn(acc.x, acc.y);
        __half2 h23 = __floats2half2_rn(acc.z, acc.w);
        uint2 pk;
        pk.x = *(uint32_t*)&h01;
        pk.y = *(uint32_t*)&h23;
        *(uint2*)(Arow + t * D + 4 * lane) = pk;
        if (lane == 0) g_cntf[bin0 + t] = (float)(end - beg);
    }
}

// ---------------- weight fp16 pre-conversion (both layers, one launch) ----------------
__global__ void cvtW(const float* __restrict__ w1, const float* __restrict__ w2) {
    int i = blockIdx.x * blockDim.x + threadIdx.x;
    if (i < WSZ) {
        g_Wh[i]       = __float2half_rn(w1[i]);
        g_Wh[WSZ + i] = __float2half_rn(w2[i]);
    }
}

// ---------------- tall fp16 GEMM: 128x128 tile, K=640, cp.async double buffer ----------------
// Optional fused BN stats for the NEXT round (gamma != nullptr).
__global__ void __launch_bounds__(256, 2) gemm_agg(
    const __half* __restrict__ W, const float* __restrict__ bias,
    const float* __restrict__ addend, float* __restrict__ out, int Nrows,
    const float* __restrict__ gamma, const float* __restrict__ beta) {
    extern __shared__ __half smh[];
    int tid = threadIdx.x;
    int row0 = blockIdx.x * 128;
    const __half* Agl = g_Ah + (size_t)row0 * NOUT;

    int warp = tid >> 5, lane = tid & 31;
    int wm = warp >> 2, wn = warp & 3;           // 2x4 warps, warp tile 64x32
    int wrow = wm * 64, wcol = wn * 32;
    int gid = lane >> 2, tig = lane & 3;

    float c[4][4][4];
    #pragma unroll
    for (int mt = 0; mt < 4; mt++)
        #pragma unroll
        for (int nt = 0; nt < 4; nt++)
            #pragma unroll
            for (int q = 0; q < 4; q++) c[mt][nt][q] = 0.f;

    const int NC = NOUT / 64;  // 10 chunks of K=64

    auto load_chunk = [&](int cidx, int buf) {
        int k0 = cidx * 64;
        int t = k0 >> 7, kd = k0 & 127;
        __half* as = smh + buf * (2 * 128 * LDH);
        __half* bs = as + 128 * LDH;
        const __half* Asrc = Agl + k0;
        const __half* Bsrc = W + ((size_t)t * 128) * 128 + kd;
        #pragma unroll
        for (int i = 0; i < 4; i++) {
            int gnum = tid + i * 256;
            int r = gnum >> 3, sg = gnum & 7;
            cp_async16(as + r * LDH + sg * 8, Asrc + (size_t)r * NOUT + sg * 8);
        }
        #pragma unroll
        for (int i = 0; i < 4; i++) {
            int gnum = tid + i * 256;
            int j = gnum >> 3, sg = gnum & 7;
            cp_async16(bs + j * LDH + sg * 8, Bsrc + (size_t)j * 128 + sg * 8);
        }
        CP_COMMIT();
    };

    load_chunk(0, 0);
    for (int cidx = 0; cidx < NC; cidx++) {
        CP_WAIT0();
        __syncthreads();
        if (cidx + 1 < NC) load_chunk(cidx + 1, (cidx + 1) & 1);
        const __half* as = smh + (cidx & 1) * (2 * 128 * LDH);
        const __half* bs = as + 128 * LDH;
        #pragma unroll
        for (int ks = 0; ks < 4; ks++) {
            int kk = ks * 16;
            uint32_t a[4][4], b[4][2];
            #pragma unroll
            for (int mt = 0; mt < 4; mt++) {
                int r = wrow + mt * 16 + gid;
                a[mt][0] = *(const uint32_t*)(as + r * LDH + kk + tig * 2);
                a[mt][1] = *(const uint32_t*)(as + (r + 8) * LDH + kk + tig * 2);
                a[mt][2] = *(const uint32_t*)(as + r * LDH + kk + tig * 2 + 8);
                a[mt][3] = *(const uint32_t*)(as + (r + 8) * LDH + kk + tig * 2 + 8);
            }
            #pragma unroll
            for (int nt = 0; nt < 4; nt++) {
                int j = wcol + nt * 8 + gid;
                b[nt][0] = *(const uint32_t*)(bs + j * LDH + kk + tig * 2);
                b[nt][1] = *(const uint32_t*)(bs + j * LDH + kk + tig * 2 + 8);
            }
            #pragma unroll
            for (int mt = 0; mt < 4; mt++)
                #pragma unroll
                for (int nt = 0; nt < 4; nt++)
                    mma_f16(c[mt][nt], a[mt], b[nt]);
        }
        __syncthreads();
    }

    // epilogue: per-(node,type) count x bias + optional residual + optional fused stats
    float* smf  = (float*)smh;
    float* cntS = smf;          // [128][5]
    float* bsm  = smf + 640;    // [5][128]
    float* ssum = smf + 1280;   // [128]
    float* ssq  = smf + 1408;   // [128]
    for (int i = tid; i < 640; i += 256) {
        int r = i / T5, t = i % T5;
        int gr = row0 + r;
        cntS[i] = (gr < Nrows) ? g_cntf[gr * T5 + t] : 0.f;
        bsm[i] = __ldg(&bias[i]);
    }
    if (tid < 128) { ssum[tid] = 0.f; ssq[tid] = 0.f; }
    __syncthreads();

    float ps[8], pq[8];
    #pragma unroll
    for (int q = 0; q < 8; q++) { ps[q] = 0.f; pq[q] = 0.f; }

    #pragma unroll
    for (int mt = 0; mt < 4; mt++) {
        #pragma unroll
        for (int half = 0; half < 2; half++) {
            int r = wrow + mt * 16 + gid + half * 8;   // 0..127
            int grow = row0 + r;
            if (grow >= Nrows) continue;
            #pragma unroll
            for (int nt = 0; nt < 4; nt++) {
                int j = wcol + nt * 8 + 2 * tig;
                float b0 = 0.f, b1 = 0.f;
                #pragma unroll
                for (int t = 0; t < T5; t++) {
                    float cn = cntS[r * T5 + t];
                    b0 = fmaf(cn, bsm[t * 128 + j], b0);
                    b1 = fmaf(cn, bsm[t * 128 + j + 1], b1);
                }
                float v0 = c[mt][nt][half * 2]     + b0;
                float v1 = c[mt][nt][half * 2 + 1] + b1;
                if (gamma) {
                    ps[nt * 2]     += v0; pq[nt * 2]     += v0 * v0;
                    ps[nt * 2 + 1] += v1; pq[nt * 2 + 1] += v1 * v1;
                }
                if (addend) {
                    float2 ad = *(const float2*)(addend + (size_t)grow * D + j);
                    v0 += ad.x; v1 += ad.y;
                }
                *(float2*)(out + (size_t)grow * D + j) = make_float2(v0, v1);
            }
        }
    }

    if (gamma) {
        #pragma unroll
        for (int nt = 0; nt < 4; nt++) {
            int j = wcol + nt * 8 + 2 * tig;
            atomicAdd(&ssum[j],     ps[nt * 2]);
            atomicAdd(&ssum[j + 1], ps[nt * 2 + 1]);
            atomicAdd(&ssq[j],      pq[nt * 2]);
            atomicAdd(&ssq[j + 1],  pq[nt * 2 + 1]);
        }
        __syncthreads();
        if (tid < 128) {
            atomicAdd(&g_stats[tid],     ssum[tid]);
            atomicAdd(&g_stats[D + tid], ssq[tid]);
        }
        __threadfence();
        __shared__ unsigned int ticket;
        if (tid == 0) ticket = atomicInc(&g_ticket2, gridDim.x - 1);
        __syncthreads();
        if (ticket == gridDim.x - 1 && tid < 128) {
            int d = tid;
            float invN = 1.0f / (float)Nrows;
            float su  = atomicAdd(&g_stats[d], 0.f);
            float sq  = atomicAdd(&g_stats[D + d], 0.f);
            float mu  = su * invN;
            float var = sq * invN - mu * mu;
            float a = gamma[d] * rsqrtf(var + EPSV);
            g_ab[d]     = a;
            g_ab[D + d] = beta[d] - a * mu;
            g_stats[d] = 0.f; g_stats[D + d] = 0.f;
        }
    }
}

// ---------------- launch ----------------
extern "C" void kernel_launch(void* const* d_in, const int* in_sizes, int n_in,
                              void* d_out, int out_size) {
    const float* features = (const float*)d_in[0];
    const int*   src      = (const int*)d_in[1];
    const int*   dst      = (const int*)d_in[2];
    const int*   etype    = (const int*)d_in[3];
    const float* w1       = (const float*)d_in[4];
    const float* b1       = (const float*)d_in[5];
    const float* g1       = (const float*)d_in[6];
    const float* be1      = (const float*)d_in[7];
    const float* w2       = (const float*)d_in[8];
    const float* b2       = (const float*)d_in[9];
    const float* g2       = (const float*)d_in[10];
    const float* be2      = (const float*)d_in[11];

    int N = in_sizes[0] / D;
    int E = in_sizes[1];

    float* tmp;
    __half* Wh;
    cudaGetSymbolAddress((void**)&tmp, g_tmp);
    cudaGetSymbolAddress((void**)&Wh, g_Wh);

    cudaFuncSetAttribute(gemm_agg, cudaFuncAttributeMaxDynamicSharedMemorySize, GEMM_SMEM);

    int gemm_blocks = (N + 127) / 128;
    int agg_blocks  = (N * 32 + 255) / 256;

    hist_kernel<<<(E + 255) / 256, 256>>>(dst, etype, E);         // 0
    scan_local<<<124, 1024>>>();                                  // 1
    scan_coarse<<<1, 128>>>();                                    // 2
    fill_csr<<<(E + 255) / 256, 256>>>(dst, etype, src, E);       // 3
    colstats<<<1184, 128>>>(features, g1, be1, N);                // 4
    aggregate<<<agg_blocks, 256>>>(features, N);                  // 5  <- ncu -s 5 profiles this
    cvtW<<<(WSZ + 255) / 256, 256>>>(w1, w2);                     // 6
    gemm_agg<<<gemm_blocks, 256, GEMM_SMEM>>>(Wh, b1, nullptr, tmp, N, g2, be2);   // 7 (stats fused)
    aggregate<<<agg_blocks, 256>>>(tmp, N);                       // 8
    gemm_agg<<<gemm_blocks, 256, GEMM_SMEM>>>(Wh + WSZ, b2, features, (float*)d_out, N,
                                              nullptr, nullptr);  // 9
}